// round 16
// baseline (speedup 1.0000x reference)
#include <cuda_runtime.h>
#include <cuda_bf16.h>
#include <math_constants.h>
#include <cstdint>

#define HH 512
#define NH 32
#define LL 8192

// l = 32a + b.  K[h, 32a+b] = sum_n MR[a,n]*VR[n,b] - MI[a,n]*VI[n,b]
// Real GEMM per h: A[256 x 64] (k=2n -> MR, k=2n+1 -> MI) times B[64 x 32]
// (k=2n -> VR, k=2n+1 -> -VI).  M[a,n] = C2_n * w_n^(32a),  V[n,b] = w_n^b.
// SINGLE fused kernel: every block regenerates its constants from the inputs.

// ---------------- helpers ----------------
static __device__ __forceinline__ float2 cmulf(float2 a, float2 b) {
    float2 r;
    r.x = fmaf(a.x, b.x, -(a.y * b.y));
    r.y = fmaf(a.x, b.y,  (a.y * b.x));
    return r;
}
static __device__ __forceinline__ float2 csqr(float2 a) {
    float2 r;
    r.x = fmaf(a.x, a.x, -(a.y * a.y));
    r.y = 2.0f * a.x * a.y;
    return r;
}

// w^p for large p, all-fp32 compensated phase reduction (no fp64).
static __device__ __forceinline__ float2 fpow(float dtar, float dtai, float p) {
    constexpr double INV2PI = 0.159154943091895335768883763372514362;
    constexpr float c_hi = (float)INV2PI;
    constexpr float c_lo = (float)(INV2PI - (double)c_hi);
    float x  = dtai * p;
    float e  = fmaf(dtai, p, -x);            // exact product residual
    float y  = x * c_hi;
    float yr = fmaf(x, c_hi, -y);            // exact product residual
    float r  = yr + fmaf(x, c_lo, e * c_hi);
    float k  = rintf(y);
    float f  = (y - k) + r;                  // frac in turns
    float s, c;
    sincospif(2.0f * f, &s, &c);
    float mag = expf(dtar * p);              // underflow to 0 == true answer
    return make_float2(mag * c, mag * s);
}

// pack complex (re, im) -> bf16x2 (re in low half) + residual pack
static __device__ __forceinline__ void bfsplit(float re, float im,
                                               uint32_t& p0, uint32_t& p1) {
    __nv_bfloat162 h0 = __float22bfloat162_rn(make_float2(re, im));
    float2 f0 = __bfloat1622float2(h0);
    __nv_bfloat162 h1 = __float22bfloat162_rn(make_float2(re - f0.x, im - f0.y));
    p0 = *reinterpret_cast<uint32_t*>(&h0);
    p1 = *reinterpret_cast<uint32_t*>(&h1);
}
static __device__ __forceinline__ void mma_bf16(float& c0, float& c1, float& c2, float& c3,
                                                uint32_t a0, uint32_t a1, uint32_t a2, uint32_t a3,
                                                uint32_t b0, uint32_t b1) {
    asm volatile(
        "mma.sync.aligned.m16n8k16.row.col.f32.bf16.bf16.f32 "
        "{%0,%1,%2,%3}, {%4,%5,%6,%7}, {%8,%9}, {%0,%1,%2,%3};"
        : "+f"(c0), "+f"(c1), "+f"(c2), "+f"(c3)
        : "r"(a0), "r"(a1), "r"(a2), "r"(a3), "r"(b0), "r"(b1));
}

// ---------------- Fused kernel ----------------
// Grid = HH*2 (h, half).  Block = 128 (4 warps).
// Warp wid handles a-tiles T = 8*half + wid + 4*tp, tp in {0,1}.
__global__ void __launch_bounds__(128, 4) s4d_fused(float* __restrict__ out,
                                                    const float* __restrict__ Cr,
                                                    const float* __restrict__ Ci,
                                                    const float* __restrict__ ldt,
                                                    const float* __restrict__ lar,
                                                    const float* __restrict__ Aim) {
    __shared__ float2 sW[NH];        // w_n
    __shared__ float2 sC2[NH];       // 2*C*(w-1)/A
    __shared__ float2 sDt[NH];       // (dtar, dtai)
    __shared__ uint32_t Bf[2048];    // fragment-packed B (hi/lo splits)

    int h    = blockIdx.x >> 1;
    int half = blockIdx.x & 1;
    int tid  = threadIdx.x;
    int wid  = tid >> 5;
    int lane = tid & 31;
    int tig  = lane & 3;             // thread-in-group
    int g    = lane >> 2;            // group id

    // ---- per-mode constants (warp 0) ----
    if (tid < NH) {
        int n = tid;
        int hn = h * NH + n;
        float dtf  = expf(ldt[h]);
        float arf  = -expf(lar[hn]);
        float aif  = Aim[hn];
        float dtar = arf * dtf;
        float dtai = aif * dtf;

        float er, si, co;
        er = expf(dtar);
        sincosf(dtai, &si, &co);
        sW[n]  = make_float2(er * co, er * si);
        sDt[n] = make_float2(dtar, dtai);

        float nr = fmaf(er, co, -1.0f), ni = er * si;   // w - 1
        float den = arf * arf + aif * aif;
        float inv = 1.0f / den;
        float fr = (nr * arf + ni * aif) * inv;
        float fi = (ni * arf - nr * aif) * inv;
        float cr = Cr[hn], ci = Ci[hn];
        sC2[n] = make_float2(2.0f * (cr * fr - ci * fi),
                             2.0f * (cr * fi + ci * fr));
    }
    __syncthreads();

    // ---- build B fragments: thread = (n = tid&31, bg = tid>>5), b = 8*bg+k ----
    {
        int n  = tid & 31;
        int bg = tid >> 5;
        float2 w  = sW[n];
        float2 w8 = csqr(csqr(csqr(w)));
        float2 v  = make_float2(1.0f, 0.0f);
        if (bg & 1) v = w8;
        if (bg & 2) v = cmulf(v, csqr(w8));              // * w^16
        int s = n >> 3;
        int libase = ((n & 3) << 1) | ((n >> 2) & 1);
        uint32_t* bf0 = Bf + ((0 * 4 + s) * 4 + bg) * 64;
        uint32_t* bf1 = Bf + ((1 * 4 + s) * 4 + bg) * 64;
        #pragma unroll
        for (int k = 0; k < 8; ++k) {
            uint32_t p0, p1;
            bfsplit(v.x, -v.y, p0, p1);                  // (VR, -VI)
            int li = (k << 3) | libase;
            bf0[li] = p0;
            bf1[li] = p1;
            v = cmulf(v, w);
        }
    }
    __syncthreads();

    // ---- generate A fragments for BOTH tiles via fpow (no table loads) ----
    int rl0 = ((wid & 1) << 4) + g;
    int rl1 = rl0 + 8;

    uint32_t A0[2][2][8], A1[2][2][8];      // [tp][row][k-pair]
    #pragma unroll
    for (int j = 0; j < 8; ++j) {
        int n = tig + 4 * j;
        float2 dt = sDt[n];
        float2 c2 = sC2[n];
        #pragma unroll
        for (int tp = 0; tp < 2; ++tp) {
            int T = 8 * half + wid + 4 * tp;
            int q = T >> 1;
            float p0f = (float)(1024 * q + 32 * rl0);    // 32*a for row 0
            float p1f = (float)(1024 * q + 32 * rl1);    // 32*a for row 1
            float2 m0 = cmulf(c2, fpow(dt.x, dt.y, p0f));
            float2 m1 = cmulf(c2, fpow(dt.x, dt.y, p1f));
            bfsplit(m0.x, m0.y, A0[tp][0][j], A1[tp][0][j]);
            bfsplit(m1.x, m1.y, A0[tp][1][j], A1[tp][1][j]);
        }
    }

    float acc[2][4][4];
    #pragma unroll
    for (int tp = 0; tp < 2; ++tp)
        #pragma unroll
        for (int m = 0; m < 4; ++m)
            #pragma unroll
            for (int k = 0; k < 4; ++k) acc[tp][m][k] = 0.0f;

    // ---- fused mma loop: 3 passes (A0*B1, A1*B0, A0*B0), B loaded once per (p,s,m) ----
    #pragma unroll
    for (int p = 0; p < 3; ++p) {
        int bsplit = (p == 0) ? 1 : 0;
        #pragma unroll
        for (int s = 0; s < 4; ++s) {
            #pragma unroll
            for (int m = 0; m < 4; ++m) {
                uint2 bb = *reinterpret_cast<const uint2*>(
                    &Bf[((bsplit * 4 + s) * 4 + m) * 64 + lane * 2]);
                #pragma unroll
                for (int tp = 0; tp < 2; ++tp) {
                    uint32_t a0 = (p == 1) ? A1[tp][0][2 * s]     : A0[tp][0][2 * s];
                    uint32_t a1 = (p == 1) ? A1[tp][1][2 * s]     : A0[tp][1][2 * s];
                    uint32_t a2 = (p == 1) ? A1[tp][0][2 * s + 1] : A0[tp][0][2 * s + 1];
                    uint32_t a3 = (p == 1) ? A1[tp][1][2 * s + 1] : A0[tp][1][2 * s + 1];
                    mma_bf16(acc[tp][m][0], acc[tp][m][1], acc[tp][m][2], acc[tp][m][3],
                             a0, a1, a2, a3, bb.x, bb.y);
                }
            }
        }
    }

    // ---- store ----
    float* oph = out + h * LL;
    #pragma unroll
    for (int tp = 0; tp < 2; ++tp) {
        int T = 8 * half + wid + 4 * tp;
        #pragma unroll
        for (int m = 0; m < 4; ++m) {
            int bc = 8 * m + 2 * tig;
            __stcs((float2*)(oph + (16 * T + g) * NH + bc),
                   make_float2(acc[tp][m][0], acc[tp][m][1]));
            __stcs((float2*)(oph + (16 * T + g + 8) * NH + bc),
                   make_float2(acc[tp][m][2], acc[tp][m][3]));
        }
    }
}

extern "C" void kernel_launch(void* const* d_in, const int* in_sizes, int n_in,
                              void* d_out, int out_size) {
    const float* C_real     = (const float*)d_in[0];
    const float* C_imag     = (const float*)d_in[1];
    const float* log_dt     = (const float*)d_in[2];
    const float* log_a_real = (const float*)d_in[3];
    const float* A_imag     = (const float*)d_in[4];
    float* out = (float*)d_out;

    s4d_fused<<<HH * 2, 128>>>(out, C_real, C_imag, log_dt, log_a_real, A_imag);
}

// round 17
// speedup vs baseline: 1.2909x; 1.2909x over previous
#include <cuda_runtime.h>
#include <cuda_bf16.h>
#include <math_constants.h>
#include <cstdint>

#define HH 512
#define NH 32
#define LL 8192

// l = 32a + b.  K[h, 32a+b] = sum_n MR[a,n]*VR[n,b] - MI[a,n]*VI[n,b]
// Real GEMM per h: A[256 x 64] (k=2n -> MR, k=2n+1 -> MI) times B[64 x 32]
// (k=2n -> VR, k=2n+1 -> -VI).  M[a,n] = C2_n * w_n^(32a),  V[n,b] = w_n^b.
// SINGLE fused kernel, one block per h; A-gen uses a factored fpow lattice.

// ---------------- helpers ----------------
static __device__ __forceinline__ float2 cmulf(float2 a, float2 b) {
    float2 r;
    r.x = fmaf(a.x, b.x, -(a.y * b.y));
    r.y = fmaf(a.x, b.y,  (a.y * b.x));
    return r;
}
static __device__ __forceinline__ float2 csqr(float2 a) {
    float2 r;
    r.x = fmaf(a.x, a.x, -(a.y * a.y));
    r.y = 2.0f * a.x * a.y;
    return r;
}

// w^p for large p, all-fp32 compensated phase reduction (no fp64).
static __device__ __forceinline__ float2 fpow(float dtar, float dtai, float p) {
    constexpr double INV2PI = 0.159154943091895335768883763372514362;
    constexpr float c_hi = (float)INV2PI;
    constexpr float c_lo = (float)(INV2PI - (double)c_hi);
    float x  = dtai * p;
    float e  = fmaf(dtai, p, -x);            // exact product residual
    float y  = x * c_hi;
    float yr = fmaf(x, c_hi, -y);            // exact product residual
    float r  = yr + fmaf(x, c_lo, e * c_hi);
    float k  = rintf(y);
    float f  = (y - k) + r;                  // frac in turns
    float s, c;
    sincospif(2.0f * f, &s, &c);
    float mag = expf(dtar * p);              // underflow to 0 == true answer
    return make_float2(mag * c, mag * s);
}

// pack complex (re, im) -> bf16x2 (re in low half) + residual pack
static __device__ __forceinline__ void bfsplit(float re, float im,
                                               uint32_t& p0, uint32_t& p1) {
    __nv_bfloat162 h0 = __float22bfloat162_rn(make_float2(re, im));
    float2 f0 = __bfloat1622float2(h0);
    __nv_bfloat162 h1 = __float22bfloat162_rn(make_float2(re - f0.x, im - f0.y));
    p0 = *reinterpret_cast<uint32_t*>(&h0);
    p1 = *reinterpret_cast<uint32_t*>(&h1);
}
static __device__ __forceinline__ void mma_bf16(float& c0, float& c1, float& c2, float& c3,
                                                uint32_t a0, uint32_t a1, uint32_t a2, uint32_t a3,
                                                uint32_t b0, uint32_t b1) {
    asm volatile(
        "mma.sync.aligned.m16n8k16.row.col.f32.bf16.bf16.f32 "
        "{%0,%1,%2,%3}, {%4,%5,%6,%7}, {%8,%9}, {%0,%1,%2,%3};"
        : "+f"(c0), "+f"(c1), "+f"(c2), "+f"(c3)
        : "r"(a0), "r"(a1), "r"(a2), "r"(a3), "r"(b0), "r"(b1));
}

// ---------------- Fused kernel: one block per h ----------------
// Block = 256 (8 warps).  Warp wid handles a-tiles T = wid + 8*tp, tp in {0,1}.
__global__ void __launch_bounds__(256, 2) s4d_fused(float* __restrict__ out,
                                                    const float* __restrict__ Cr,
                                                    const float* __restrict__ Ci,
                                                    const float* __restrict__ ldt,
                                                    const float* __restrict__ lar,
                                                    const float* __restrict__ Aim) {
    __shared__ float2 sW[NH];        // w_n
    __shared__ float2 sC2[NH];       // 2*C*(w-1)/A
    __shared__ float2 sDt[NH];       // (dtar, dtai)
    __shared__ float2 sW256[NH];     // w^256  (row +8 jump: 32*8)
    __shared__ float2 sW4096[NH];    // w^4096 (tile +8 jump: 1024*4)
    __shared__ uint32_t Bf[2048];    // fragment-packed B (hi/lo splits)

    int h    = blockIdx.x;
    int tid  = threadIdx.x;
    int wid  = tid >> 5;
    int lane = tid & 31;
    int tig  = lane & 3;             // thread-in-group
    int g    = lane >> 2;            // group id

    // ---- per-mode constants (first warp) ----
    if (tid < NH) {
        int n = tid;
        int hn = h * NH + n;
        float dtf  = expf(ldt[h]);
        float arf  = -expf(lar[hn]);
        float aif  = Aim[hn];
        float dtar = arf * dtf;
        float dtai = aif * dtf;

        float er, si, co;
        er = expf(dtar);
        sincosf(dtai, &si, &co);
        sW[n]  = make_float2(er * co, er * si);
        sDt[n] = make_float2(dtar, dtai);

        float nr = fmaf(er, co, -1.0f), ni = er * si;   // w - 1
        float den = arf * arf + aif * aif;
        float inv = 1.0f / den;
        float fr = (nr * arf + ni * aif) * inv;
        float fi = (ni * arf - nr * aif) * inv;
        float cr = Cr[hn], ci = Ci[hn];
        sC2[n] = make_float2(2.0f * (cr * fr - ci * fi),
                             2.0f * (cr * fi + ci * fr));

        sW256[n]  = fpow(dtar, dtai, 256.0f);
        sW4096[n] = fpow(dtar, dtai, 4096.0f);
    }
    __syncthreads();

    // ---- build B fragments: thread = (n, bg, kh); b = 8*bg + 4*kh + k ----
    {
        int n  = tid & 31;
        int bg = (tid >> 5) & 3;
        int kh = tid >> 7;                               // 0/1
        float2 w  = sW[n];
        float2 w4 = csqr(csqr(w));
        float2 w8 = csqr(w4);
        float2 v  = make_float2(1.0f, 0.0f);
        if (bg & 1) v = w8;
        if (bg & 2) v = cmulf(v, csqr(w8));              // * w^16
        if (kh)     v = cmulf(v, w4);
        int s = n >> 3;
        int libase = ((n & 3) << 1) | ((n >> 2) & 1);
        uint32_t* bf0 = Bf + ((0 * 4 + s) * 4 + bg) * 64;
        uint32_t* bf1 = Bf + ((1 * 4 + s) * 4 + bg) * 64;
        #pragma unroll
        for (int k = 0; k < 4; ++k) {
            uint32_t p0, p1;
            bfsplit(v.x, -v.y, p0, p1);                  // (VR, -VI)
            int li = ((4 * kh + k) << 3) | libase;
            bf0[li] = p0;
            bf1[li] = p1;
            v = cmulf(v, w);
        }
    }
    __syncthreads();

    // ---- A fragments for both tiles via factored fpow lattice ----
    int rl0 = ((wid & 1) << 4) + g;                      // row (a & 31), row 0
    int q0  = wid >> 1;                                  // a>>5 for tp = 0

    uint32_t A0[2][2][8], A1[2][2][8];      // [tp][row][k-pair]
    #pragma unroll
    for (int j = 0; j < 8; ++j) {
        int n = tig + 4 * j;
        float2 dt  = sDt[n];
        float2 c2  = sC2[n];
        float2 j8  = sW256[n];
        float2 j8t = sW4096[n];
        // base: M[tp=0, row0] ; others by fixed-offset complex multiplies
        float2 m00 = cmulf(c2, fpow(dt.x, dt.y, (float)(1024 * q0 + 32 * rl0)));
        float2 m01 = cmulf(m00, j8);                     // row +8
        float2 m10 = cmulf(m00, j8t);                    // tile +8 (a += 256)
        float2 m11 = cmulf(m10, j8);
        bfsplit(m00.x, m00.y, A0[0][0][j], A1[0][0][j]);
        bfsplit(m01.x, m01.y, A0[0][1][j], A1[0][1][j]);
        bfsplit(m10.x, m10.y, A0[1][0][j], A1[1][0][j]);
        bfsplit(m11.x, m11.y, A0[1][1][j], A1[1][1][j]);
    }

    float acc[2][4][4];
    #pragma unroll
    for (int tp = 0; tp < 2; ++tp)
        #pragma unroll
        for (int m = 0; m < 4; ++m)
            #pragma unroll
            for (int k = 0; k < 4; ++k) acc[tp][m][k] = 0.0f;

    // ---- fused mma loop: 3 passes (A0*B1, A1*B0, A0*B0), B loaded once per (p,s,m) ----
    #pragma unroll
    for (int p = 0; p < 3; ++p) {
        int bsplit = (p == 0) ? 1 : 0;
        #pragma unroll
        for (int s = 0; s < 4; ++s) {
            #pragma unroll
            for (int m = 0; m < 4; ++m) {
                uint2 bb = *reinterpret_cast<const uint2*>(
                    &Bf[((bsplit * 4 + s) * 4 + m) * 64 + lane * 2]);
                #pragma unroll
                for (int tp = 0; tp < 2; ++tp) {
                    uint32_t a0 = (p == 1) ? A1[tp][0][2 * s]     : A0[tp][0][2 * s];
                    uint32_t a1 = (p == 1) ? A1[tp][1][2 * s]     : A0[tp][1][2 * s];
                    uint32_t a2 = (p == 1) ? A1[tp][0][2 * s + 1] : A0[tp][0][2 * s + 1];
                    uint32_t a3 = (p == 1) ? A1[tp][1][2 * s + 1] : A0[tp][1][2 * s + 1];
                    mma_bf16(acc[tp][m][0], acc[tp][m][1], acc[tp][m][2], acc[tp][m][3],
                             a0, a1, a2, a3, bb.x, bb.y);
                }
            }
        }
    }

    // ---- store ----
    float* oph = out + h * LL;
    #pragma unroll
    for (int tp = 0; tp < 2; ++tp) {
        int T = wid + 8 * tp;
        #pragma unroll
        for (int m = 0; m < 4; ++m) {
            int bc = 8 * m + 2 * tig;
            __stcs((float2*)(oph + (16 * T + g) * NH + bc),
                   make_float2(acc[tp][m][0], acc[tp][m][1]));
            __stcs((float2*)(oph + (16 * T + g + 8) * NH + bc),
                   make_float2(acc[tp][m][2], acc[tp][m][3]));
        }
    }
}

extern "C" void kernel_launch(void* const* d_in, const int* in_sizes, int n_in,
                              void* d_out, int out_size) {
    const float* C_real     = (const float*)d_in[0];
    const float* C_imag     = (const float*)d_in[1];
    const float* log_dt     = (const float*)d_in[2];
    const float* log_a_real = (const float*)d_in[3];
    const float* A_imag     = (const float*)d_in[4];
    float* out = (float*)d_out;

    s4d_fused<<<HH, 256>>>(out, C_real, C_imag, log_dt, log_a_real, A_imag);
}